// round 13
// baseline (speedup 1.0000x reference)
#include <cuda_runtime.h>

#define TT 512
#define BB 512
#define KK 64
#define STRD (BB*KK)
#define LOG2E 1.4426950408889634f
#define LN2   0.6931471805599453f

typedef unsigned long long ull;

// scratch (device globals — no allocation)
__device__ float g_partial[BB];
__device__ int   g_cntp[64];   // detect partials, plain-stored each replay
__device__ int   g_done;       // reset by detect block 0 each replay

__device__ __forceinline__ float ex2f_(float x){float y;asm("ex2.approx.f32 %0,%1;":"=f"(y):"f"(x));return y;}
__device__ __forceinline__ float lg2f_(float x){float y;asm("lg2.approx.f32 %0,%1;":"=f"(y):"f"(x));return y;}
__device__ __forceinline__ ull fma2_(ull a,ull b,ull c){ull d;asm("fma.rn.f32x2 %0,%1,%2,%3;":"=l"(d):"l"(a),"l"(b),"l"(c));return d;}
__device__ __forceinline__ ull add2_(ull a,ull b){ull d;asm("add.rn.f32x2 %0,%1,%2;":"=l"(d):"l"(a),"l"(b));return d;}
__device__ __forceinline__ ull pack2_(float lo,float hi){ull d;asm("mov.b64 %0,{%1,%2};":"=l"(d):"f"(lo),"f"(hi));return d;}
__device__ __forceinline__ float2 unpack2_(ull v){float2 r;asm("mov.b64 {%0,%1},%2;":"=f"(r.x),"=f"(r.y):"l"(v));return r;}

#define CNTB(u) ((((u)&0xFFu)!=0)+(((u)&0xFF00u)!=0)+(((u)&0xFF0000u)!=0)+(((u)&0xFF000000u)!=0))

// ---------------------------------------------------------------------------
// Detect: 64 blocks x 256 threads, one uint4 per thread over the first TT*BB
// bytes of the mask (safe under bool/int32/f32 serializations). A 1-byte
// one-hot mask has exactly BB nonzero bytes total. Plain stores: idempotent
// across graph replays. Block 0 also resets the forward completion counter.
// ---------------------------------------------------------------------------
__global__ __launch_bounds__(256) void detect_kernel(const unsigned char* __restrict__ m)
{
    __shared__ int w_s[8];
    const int tid = threadIdx.x;
    if (blockIdx.x == 0 && tid == 0) g_done = 0;
    uint4 v = ((const uint4*)m)[blockIdx.x * 256 + tid];
    int local = CNTB(v.x) + CNTB(v.y) + CNTB(v.z) + CNTB(v.w);
    #pragma unroll
    for (int o = 16; o > 0; o >>= 1) local += __shfl_xor_sync(0xffffffffu, local, o);
    if ((tid & 31) == 0) w_s[tid >> 5] = local;
    __syncthreads();
    if (tid == 0) {
        int s = 0;
        #pragma unroll
        for (int k = 0; k < 8; k++) s += w_s[k];
        g_cntp[blockIdx.x] = s;
    }
}

// ---------------------------------------------------------------------------
// Forward: 512 CTAs x 128 threads, ONE batch per CTA, TWO threads per state
// column. Thread (j = 16*warp + lane/2, h = lane&1) computes the half-sum
//   partial = sum_{i in [32h, 32h+32)} P_i * E_ij        (16 fma2, 8 LDS.128)
// then S_j = partial + shfl_xor(partial, 1)  (partner = adjacent lane).
// Halves per-warp instructions vs 1-thread/column and spreads the batch over
// all 4 SMSPs (wid%4) WITHOUT coupling two batches (no ghost steps - R12 bug).
// p is stored split: lo j<32 at [j], hi at [40 + j-32] (16B-aligned pad ->
// the two per-instruction broadcast addresses hit disjoint banks).
// EXPONENT-ONLY pivot renorm (exact):
//   eb = expfield(P_0^{t-1}) ; c = 2^(127-eb) ; P'_j = S_j*em_j*c ; C2i += eb
// Invariant: log2 alpha_j = lg2(P_j) + (C2i - 127*t).
// Final per-b: LN2*((C2i-127*stop) + lg2(sum_j P_j)). Last CTA does 512->1.
// ---------------------------------------------------------------------------
__global__ __launch_bounds__(128, 8)
void crf_forward_kernel(const float* __restrict__ emits,
                        const unsigned char* __restrict__ mask,
                        const float* __restrict__ trans,
                        const float* __restrict__ alpha0,
                        float* __restrict__ out)
{
    __shared__ float p_s[2][72];      // [buf][lo:0..31, pad, hi:40..71]
    __shared__ float red_s[4];
    __shared__ int   stop_sh;
    __shared__ int   is4_sh;
    __shared__ int   last_s;

    const int tid  = threadIdx.x;
    const int w    = tid >> 5;
    const int lane = tid & 31;
    const int j    = (w << 4) | (lane >> 1);   // state column 0..63
    const int h    = lane & 1;                 // half of the K-sum
    const int b    = blockIdx.x;
    const int sidx = j + ((j >> 5) << 3);      // split-layout index (+8 pad for hi)

    if (tid == 0) stop_sh = 0;

    // mask dtype: warp 0 sums the 64 detect partials
    if (tid < 32) {
        int c0 = g_cntp[tid] + g_cntp[tid + 32];
        #pragma unroll
        for (int o = 16; o > 0; o >>= 1) c0 += __shfl_xor_sync(0xffffffffu, c0, o);
        if (tid == 0) is4_sh = (c0 != BB);
    }
    __syncthreads();
    const bool is4 = is4_sh;

    // stop index: one-hot => exactly one thread fires the atomic
    if (is4) {
        const unsigned* m4 = (const unsigned*)mask;
        #pragma unroll
        for (int k = 0; k < TT / 128; k++) {
            int t = tid + 128 * k;
            if (m4[t * BB + b]) atomicMax(&stop_sh, t);
        }
    } else {
        #pragma unroll
        for (int k = 0; k < TT / 128; k++) {
            int t = tid + 128 * k;
            if (mask[t * BB + b]) atomicMax(&stop_sh, t);
        }
    }

    // E = exp(trans): rows [32h, 32h+32) of column j, packed over row-pairs
    ull tr2[16];
    #pragma unroll
    for (int m = 0; m < 16; m++)
        tr2[m] = pack2_(ex2f_(trans[(32*h + 2*m    )*KK + j] * LOG2E),
                        ex2f_(trans[(32*h + 2*m + 1)*KK + j] * LOG2E));

    __syncthreads();
    const int stop = stop_sh;   // uniform

    const float* ep = emits + b * KK + j;
    float P = ex2f_((alpha0[j] + ep[0]) * LOG2E);
    if (h == 0) p_s[0][sidx] = P;
    int C2i = 0;                // exact pivot-exponent sum (valid on h==0 lanes)

    // emit pipeline depth 4 (lane pairs load the same addr -> 1 request)
    float em = ex2f_(ep[min(1, stop) * STRD] * LOG2E);
    float rA = ep[min(2, stop) * STRD];
    float rB = ep[min(3, stop) * STRD];
    float rC = ep[min(4, stop) * STRD];

    __syncthreads();

    // One step: read p_s[RB] (own half), write p_s[WB] (h==0 lanes only).
#define CRF_STEP(RB, WB, TCUR, EMIT, RNEXT, LDREG, NEWEM)                      \
    {                                                                          \
        const float LDREG = ep[(long)min((TCUR) + 4, stop) * STRD];            \
        const ulonglong2* p2 = (const ulonglong2*)&p_s[RB][h * 40];            \
        ulonglong2 v0 = p2[0];                                                 \
        /* pivot: h==0 lanes see P_0 in v0.x low; h==1 values unused */        \
        const int eb = ((int)(__float_as_uint(unpack2_(v0.x).x) >> 23));       \
        C2i += eb;                                                             \
        const float c = __int_as_float((254 - eb) << 23);  /* exact 2^-e */    \
        const float emc = (EMIT) * c;                                          \
        ull a0 = fma2_(v0.x, tr2[0], 0ull);                                    \
        ull a1 = fma2_(v0.y, tr2[1], 0ull);                                    \
        ulonglong2 w1 = p2[1];                                                 \
        ull a2 = fma2_(w1.x, tr2[2], 0ull);                                    \
        ull a3 = fma2_(w1.y, tr2[3], 0ull);                                    \
        _Pragma("unroll")                                                      \
        for (int i = 1; i < 4; i++) {                                          \
            ulonglong2 v = p2[2*i], u = p2[2*i+1];                             \
            a0 = fma2_(v.x, tr2[4*i+0], a0);                                   \
            a1 = fma2_(v.y, tr2[4*i+1], a1);                                   \
            a2 = fma2_(u.x, tr2[4*i+2], a2);                                   \
            a3 = fma2_(u.y, tr2[4*i+3], a3);                                   \
        }                                                                      \
        float2 f = unpack2_(add2_(add2_(a0, a1), add2_(a2, a3)));              \
        const float partial = f.x + f.y;                                       \
        const float S = partial + __shfl_xor_sync(0xffffffffu, partial, 1);    \
        P = S * emc;                                                           \
        if (h == 0) p_s[WB][sidx] = P;           /* predicated STS */          \
        __syncthreads();                                                       \
        const float NEWEM = ex2f_((RNEXT) * LOG2E);  /* post-bar, private */   \
        (void)NEWEM;

#define CRF_END }

    int t = 1;
    for (; t + 3 <= stop; t += 4) {
        CRF_STEP(0, 1, t,     em,  rA, ld0, em1)
        CRF_STEP(1, 0, t + 1, em1, rB, ld1, em2)
        CRF_STEP(0, 1, t + 2, em2, rC, ld2, em3)
        CRF_STEP(1, 0, t + 3, em3, ld0, ld3, em4)
        em = em4; rA = ld1; rB = ld2; rC = ld3;
        CRF_END CRF_END CRF_END CRF_END
    }
    for (; t <= stop; t++) {
        if ((t & 1) == 1) {
            CRF_STEP(0, 1, t, em, rA, lde, eme)
            em = eme; rA = rB; rB = rC; rC = lde;
            CRF_END
        } else {
            CRF_STEP(1, 0, t, em, rA, lde, eme)
            em = eme; rA = rB; rB = rC; rC = lde;
            CRF_END
        }
    }
#undef CRF_STEP
#undef CRF_END

    // per-b logZ: each column's final P lives on its h==0 lane
    float v = (h == 0) ? P : 0.f;
    #pragma unroll
    for (int o = 16; o > 0; o >>= 1) v += __shfl_xor_sync(0xffffffffu, v, o);
    if (lane == 0) red_s[w] = v;
    __syncthreads();
    if (tid == 0) {
        const float stot = (red_s[0] + red_s[1]) + (red_s[2] + red_s[3]);
        const float C2 = (float)(C2i - 127 * stop);
        g_partial[b] = LN2 * (C2 + lg2f_(stot));
        __threadfence();
        last_s = (atomicAdd(&g_done, 1) == BB - 1);
    }
    __syncthreads();

    if (last_s) {                      // deterministic 512->1 sum, 128 threads
        __threadfence();
        float s = 0.f;
        #pragma unroll
        for (int k = 0; k < BB / 128; k++) s += g_partial[tid + 128 * k];
        #pragma unroll
        for (int o = 16; o > 0; o >>= 1) s += __shfl_xor_sync(0xffffffffu, s, o);
        if (lane == 0) red_s[w] = s;
        __syncthreads();
        if (tid == 0) out[0] = (red_s[0] + red_s[1]) + (red_s[2] + red_s[3]);
    }
}

extern "C" void kernel_launch(void* const* d_in, const int* in_sizes, int n_in,
                              void* d_out, int out_size)
{
    // Identify inputs by element count (robust to metadata ordering):
    // emits 16777216, mask 262144, trans 4096, alpha0 64.
    const float*         emits  = 0;
    const unsigned char* mask   = 0;
    const float*         trans  = 0;
    const float*         alpha0 = 0;
    for (int i = 0; i < n_in; i++) {
        switch (in_sizes[i]) {
            case 16777216: emits  = (const float*)d_in[i];         break;
            case   262144: mask   = (const unsigned char*)d_in[i]; break;
            case     4096: trans  = (const float*)d_in[i];         break;
            case       64: alpha0 = (const float*)d_in[i];         break;
        }
    }
    detect_kernel<<<64, 256>>>(mask);
    crf_forward_kernel<<<BB, 128>>>(emits, mask, trans, alpha0, (float*)d_out);
}

// round 14
// speedup vs baseline: 1.2390x; 1.2390x over previous
#include <cuda_runtime.h>

#define TT 512
#define BB 512
#define KK 64
#define STRD (BB*KK)
#define LOG2E 1.4426950408889634f
#define LN2   0.6931471805599453f

typedef unsigned long long ull;

// scratch (device globals — no allocation)
__device__ float g_partial[BB];
__device__ int   g_cntp[64];   // detect partials, plain-stored each replay
__device__ int   g_done;       // reset by detect block 0 each replay

__device__ __forceinline__ float ex2f_(float x){float y;asm("ex2.approx.f32 %0,%1;":"=f"(y):"f"(x));return y;}
__device__ __forceinline__ float lg2f_(float x){float y;asm("lg2.approx.f32 %0,%1;":"=f"(y):"f"(x));return y;}
__device__ __forceinline__ ull fma2_(ull a,ull b,ull c){ull d;asm("fma.rn.f32x2 %0,%1,%2,%3;":"=l"(d):"l"(a),"l"(b),"l"(c));return d;}
__device__ __forceinline__ ull add2_(ull a,ull b){ull d;asm("add.rn.f32x2 %0,%1,%2;":"=l"(d):"l"(a),"l"(b));return d;}
__device__ __forceinline__ ull pack2_(float lo,float hi){ull d;asm("mov.b64 %0,{%1,%2};":"=l"(d):"f"(lo),"f"(hi));return d;}
__device__ __forceinline__ float2 unpack2_(ull v){float2 r;asm("mov.b64 {%0,%1},%2;":"=f"(r.x),"=f"(r.y):"l"(v));return r;}

#define CNTB(u) ((((u)&0xFFu)!=0)+(((u)&0xFF00u)!=0)+(((u)&0xFF0000u)!=0)+(((u)&0xFF000000u)!=0))

// ---------------------------------------------------------------------------
// Detect: 64 blocks x 256 threads, one uint4 per thread over the first TT*BB
// bytes of the mask (safe under bool/int32/f32 serializations). A 1-byte
// one-hot mask has exactly BB nonzero bytes total. Plain stores: idempotent
// across graph replays. Block 0 also resets the forward completion counter.
// ---------------------------------------------------------------------------
__global__ __launch_bounds__(256) void detect_kernel(const unsigned char* __restrict__ m)
{
    __shared__ int w_s[8];
    const int tid = threadIdx.x;
    if (blockIdx.x == 0 && tid == 0) g_done = 0;
    uint4 v = ((const uint4*)m)[blockIdx.x * 256 + tid];
    int local = CNTB(v.x) + CNTB(v.y) + CNTB(v.z) + CNTB(v.w);
    #pragma unroll
    for (int o = 16; o > 0; o >>= 1) local += __shfl_xor_sync(0xffffffffu, local, o);
    if ((tid & 31) == 0) w_s[tid >> 5] = local;
    __syncthreads();
    if (tid == 0) {
        int s = 0;
        #pragma unroll
        for (int k = 0; k < 8; k++) s += w_s[k];
        g_cntp[blockIdx.x] = s;
    }
}

// ---------------------------------------------------------------------------
// Forward: 128 CTAs x 128 threads; warp w INDEPENDENTLY runs batch 4*cta+w.
// 512 warps over 592 SMSPs (~0.86/SMSP) -> no issue-port sharing, and the
// loop needs only __syncwarp (23 cyc), never a block barrier.
// Lane l owns state-columns l and l+32; one broadcast read of p (8 LDS.128)
// feeds BOTH columns' FMAs (64 fma2). EXPONENT-ONLY pivot renorm (exact):
//   eb = expfield(P_0^{t-1}) ; c = 2^(127-eb) ; P' = S*em*c ; C2i += eb
// Invariant: log2 alpha_j = lg2(P_j) + (C2i - 127*t).
// Final per-b: LN2*((C2i-127*stop) + lg2(sum_j P_j)). Last warp does 512->1.
// ---------------------------------------------------------------------------
__global__ __launch_bounds__(128, 1)
void crf_forward_kernel(const float* __restrict__ emits,
                        const unsigned char* __restrict__ mask,
                        const float* __restrict__ trans,
                        const float* __restrict__ alpha0,
                        float* __restrict__ out)
{
    __shared__ float p_s[4][2][KK];   // [warp][buf][state]
    __shared__ int   is4_sh;

    const int tid  = threadIdx.x;
    const int w    = tid >> 5;
    const int l    = tid & 31;
    const int b    = 4 * blockIdx.x + w;

    // mask dtype: warp 0 sums the 64 detect partials (once per CTA)
    if (tid < 32) {
        int c0 = g_cntp[tid] + g_cntp[tid + 32];
        #pragma unroll
        for (int o = 16; o > 0; o >>= 1) c0 += __shfl_xor_sync(0xffffffffu, c0, o);
        if (tid == 0) is4_sh = (c0 != BB);
    }
    __syncthreads();                   // ONLY block barrier in this kernel
    const bool is4 = is4_sh;

    // stop index for batch b (warp-local scan + max reduce)
    int stop = 0;
    if (is4) {
        const unsigned* m4 = (const unsigned*)mask;
        #pragma unroll
        for (int k = 0; k < TT / 32; k++) {
            int t = l + 32 * k;
            if (m4[t * BB + b]) stop = t;
        }
    } else {
        #pragma unroll
        for (int k = 0; k < TT / 32; k++) {
            int t = l + 32 * k;
            if (mask[t * BB + b]) stop = t;
        }
    }
    #pragma unroll
    for (int o = 16; o > 0; o >>= 1) stop = max(stop, __shfl_xor_sync(0xffffffffu, stop, o));

    // E = exp(trans): columns l and l+32, packed over i-pairs (128 regs)
    ull tr2a[KK / 2], tr2b[KK / 2];
    #pragma unroll
    for (int m = 0; m < KK / 2; m++) {
        tr2a[m] = pack2_(ex2f_(trans[(2*m)*KK + l     ] * LOG2E),
                         ex2f_(trans[(2*m+1)*KK + l   ] * LOG2E));
        tr2b[m] = pack2_(ex2f_(trans[(2*m)*KK + l + 32] * LOG2E),
                         ex2f_(trans[(2*m+1)*KK + l+32] * LOG2E));
    }

    const float* ep0 = emits + b * KK + l;
    const float* ep1 = ep0 + 32;
    float P0 = ex2f_((alpha0[l]      + ep0[0]) * LOG2E);
    float P1 = ex2f_((alpha0[l + 32] + ep1[0]) * LOG2E);
    p_s[w][0][l]      = P0;
    p_s[w][0][l + 32] = P1;
    int C2i = 0;                       // exact pivot-exponent sum

    // emit pipeline depth 4, two streams (cols l and l+32)
    float em0 = ex2f_(ep0[min(1, stop) * STRD] * LOG2E);
    float em1 = ex2f_(ep1[min(1, stop) * STRD] * LOG2E);
    float rA0 = ep0[min(2, stop) * STRD], rA1 = ep1[min(2, stop) * STRD];
    float rB0 = ep0[min(3, stop) * STRD], rB1 = ep1[min(3, stop) * STRD];
    float rC0 = ep0[min(4, stop) * STRD], rC1 = ep1[min(4, stop) * STRD];

    __syncwarp();

    // One step: read p_s[w][RB], write p_s[w][WB]. Emit loads min-clamped
    // (clamped raws never consumed). NEWEM* converted after the syncwarp.
#define CRF_STEP(RB, WB, TCUR, EM0, EM1, RN0, RN1, LD0, LD1, NE0, NE1)         \
    {                                                                          \
        const float LD0 = ep0[(long)min((TCUR) + 4, stop) * STRD];             \
        const float LD1 = ep1[(long)min((TCUR) + 4, stop) * STRD];             \
        const ulonglong2* p2 = (const ulonglong2*)p_s[w][RB];                  \
        ulonglong2 v0 = p2[0];                                                 \
        const int eb = ((int)(__float_as_uint(unpack2_(v0.x).x) >> 23));       \
        C2i += eb;                                                             \
        const float c = __int_as_float((254 - eb) << 23);   /* exact 2^-e */   \
        const float emc0 = (EM0) * c, emc1 = (EM1) * c;                        \
        ull a0 = fma2_(v0.x, tr2a[0], 0ull);                                   \
        ull a1 = fma2_(v0.y, tr2a[1], 0ull);                                   \
        ull b0 = fma2_(v0.x, tr2b[0], 0ull);                                   \
        ull b1 = fma2_(v0.y, tr2b[1], 0ull);                                   \
        ulonglong2 u0 = p2[1];                                                 \
        ull a2 = fma2_(u0.x, tr2a[2], 0ull);                                   \
        ull a3 = fma2_(u0.y, tr2a[3], 0ull);                                   \
        ull b2 = fma2_(u0.x, tr2b[2], 0ull);                                   \
        ull b3 = fma2_(u0.y, tr2b[3], 0ull);                                   \
        _Pragma("unroll")                                                      \
        for (int i = 1; i < 8; i++) {                                          \
            ulonglong2 v = p2[2*i], u = p2[2*i+1];                             \
            a0 = fma2_(v.x, tr2a[4*i+0], a0);                                  \
            a1 = fma2_(v.y, tr2a[4*i+1], a1);                                  \
            b0 = fma2_(v.x, tr2b[4*i+0], b0);                                  \
            b1 = fma2_(v.y, tr2b[4*i+1], b1);                                  \
            a2 = fma2_(u.x, tr2a[4*i+2], a2);                                  \
            a3 = fma2_(u.y, tr2a[4*i+3], a3);                                  \
            b2 = fma2_(u.x, tr2b[4*i+2], b2);                                  \
            b3 = fma2_(u.y, tr2b[4*i+3], b3);                                  \
        }                                                                      \
        float2 fa = unpack2_(add2_(add2_(a0, a1), add2_(a2, a3)));             \
        float2 fb = unpack2_(add2_(add2_(b0, b1), add2_(b2, b3)));             \
        P0 = (fa.x + fa.y) * emc0;                                             \
        P1 = (fb.x + fb.y) * emc1;                                             \
        p_s[w][WB][l]      = P0;                                               \
        p_s[w][WB][l + 32] = P1;                                               \
        __syncwarp();                                                          \
        const float NE0 = ex2f_((RN0) * LOG2E);      /* post-sync, private */  \
        const float NE1 = ex2f_((RN1) * LOG2E);                                \
        (void)NE0; (void)NE1;

#define CRF_END }

    int t = 1;
    for (; t + 1 <= stop; t += 2) {
        CRF_STEP(0, 1, t,     em0, em1, rA0, rA1, ld0, ld1, ne0, ne1)
        CRF_STEP(1, 0, t + 1, ne0, ne1, rB0, rB1, ld2, ld3, ne2, ne3)
        em0 = ne2; em1 = ne3;
        rA0 = rC0; rA1 = rC1;
        rB0 = ld0; rB1 = ld1;
        rC0 = ld2; rC1 = ld3;
        CRF_END CRF_END
    }
    if (t <= stop) {
        CRF_STEP(0, 1, t, em0, em1, rA0, rA1, lde0, lde1, nee0, nee1)
        CRF_END
    }
#undef CRF_STEP
#undef CRF_END

    // per-b logZ (warp-local)
    float v = P0 + P1;
    #pragma unroll
    for (int o = 16; o > 0; o >>= 1) v += __shfl_xor_sync(0xffffffffu, v, o);
    int last = 0;
    if (l == 0) {
        const float C2 = (float)(C2i - 127 * stop);
        g_partial[b] = LN2 * (C2 + lg2f_(v));
        __threadfence();
        last = (atomicAdd(&g_done, 1) == BB - 1);
    }
    last = __shfl_sync(0xffffffffu, last, 0);

    if (last) {                        // deterministic 512->1 sum, one warp
        __threadfence();
        float s = 0.f;
        #pragma unroll
        for (int k = 0; k < BB / 32; k++) s += g_partial[l + 32 * k];
        #pragma unroll
        for (int o = 16; o > 0; o >>= 1) s += __shfl_xor_sync(0xffffffffu, s, o);
        if (l == 0) out[0] = s;
    }
}

extern "C" void kernel_launch(void* const* d_in, const int* in_sizes, int n_in,
                              void* d_out, int out_size)
{
    // Identify inputs by element count (robust to metadata ordering):
    // emits 16777216, mask 262144, trans 4096, alpha0 64.
    const float*         emits  = 0;
    const unsigned char* mask   = 0;
    const float*         trans  = 0;
    const float*         alpha0 = 0;
    for (int i = 0; i < n_in; i++) {
        switch (in_sizes[i]) {
            case 16777216: emits  = (const float*)d_in[i];         break;
            case   262144: mask   = (const unsigned char*)d_in[i]; break;
            case     4096: trans  = (const float*)d_in[i];         break;
            case       64: alpha0 = (const float*)d_in[i];         break;
        }
    }
    detect_kernel<<<64, 256>>>(mask);
    crf_forward_kernel<<<BB / 4, 128>>>(emits, mask, trans, alpha0, (float*)d_out);
}

// round 16
// speedup vs baseline: 1.3255x; 1.0697x over previous
#include <cuda_runtime.h>
#include <cuda_fp16.h>

#define TT 512
#define BB 512
#define KK 64
#define STRD (BB*KK)
#define LOG2E 1.4426950408889634f
#define LN2   0.6931471805599453f

typedef unsigned long long ull;

// scratch (device globals — no allocation)
__device__ float g_partial[BB];
__device__ int   g_cntp[64];   // detect partials, plain-stored each replay
__device__ int   g_done;       // reset by detect block 0 each replay

__device__ __forceinline__ float ex2f_(float x){float y;asm("ex2.approx.f32 %0,%1;":"=f"(y):"f"(x));return y;}
__device__ __forceinline__ float lg2f_(float x){float y;asm("lg2.approx.f32 %0,%1;":"=f"(y):"f"(x));return y;}

#define CNTB(u) ((((u)&0xFFu)!=0)+(((u)&0xFF00u)!=0)+(((u)&0xFF0000u)!=0)+(((u)&0xFF000000u)!=0))

// ---------------------------------------------------------------------------
// Detect: 64 blocks x 256 threads, one uint4 per thread over the first TT*BB
// bytes of the mask (safe under bool/int32/f32 serializations). A 1-byte
// one-hot mask has exactly BB nonzero bytes total. Plain stores: idempotent
// across graph replays. Block 0 also resets the forward completion counter.
// ---------------------------------------------------------------------------
__global__ __launch_bounds__(256) void detect_kernel(const unsigned char* __restrict__ m)
{
    __shared__ int w_s[8];
    const int tid = threadIdx.x;
    if (blockIdx.x == 0 && tid == 0) g_done = 0;
    uint4 v = ((const uint4*)m)[blockIdx.x * 256 + tid];
    int local = CNTB(v.x) + CNTB(v.y) + CNTB(v.z) + CNTB(v.w);
    #pragma unroll
    for (int o = 16; o > 0; o >>= 1) local += __shfl_xor_sync(0xffffffffu, local, o);
    if ((tid & 31) == 0) w_s[tid >> 5] = local;
    __syncthreads();
    if (tid == 0) {
        int s = 0;
        #pragma unroll
        for (int k = 0; k < 8; k++) s += w_s[k];
        g_cntp[blockIdx.x] = s;
    }
}

// ---------------------------------------------------------------------------
// Forward: 128 CTAs x 128 threads; warp w INDEPENDENTLY runs batch 4*cta+w
// (only __syncwarp in the loop). Lane l owns state-columns l and l+32.
// FP16 matvec (HFMA2 rt2 = 2 MACs/slot, 2x the fp32 rate):
//   Q stored as 32 x half2, slot k = (Q_k, Q_{k+32}), CURRENT-MAX normalized
//   so Qmax in [1,2) -> fp16 sum <= 2*90*64 ~ 11.5k << 65504 (no overflow).
//   E prepacked half2 e2a/e2b[k] = (E[k][j], E[k+32][j]).
// Per step: S (fp16) -> R = S*em (fp32) -> m = REDUX-max of exponent(R)
//   (single __reduce_max_sync, no shfl chain) -> Q = R*2^(127-m) exact,
//   C2i += m (exact int). em and the multiplies stay fp32.
// Invariant: log2 alpha_j = lg2(Q_j) + (C2i - 127*(t+1)).
// Final per-b: LN2*((C2i-127*(stop+1)) + lg2(sum_j Q_j)). Last warp: 512->1.
// ---------------------------------------------------------------------------
__global__ __launch_bounds__(128, 1)
void crf_forward_kernel(const float* __restrict__ emits,
                        const unsigned char* __restrict__ mask,
                        const float* __restrict__ trans,
                        const float* __restrict__ alpha0,
                        float* __restrict__ out)
{
    __shared__ __align__(16) __half2 p_s[4][2][32];   // [warp][buf][pair-slot]
    __shared__ int is4_sh;

    const int tid  = threadIdx.x;
    const int w    = tid >> 5;
    const int l    = tid & 31;
    const int b    = 4 * blockIdx.x + w;

    // mask dtype: warp 0 sums the 64 detect partials (once per CTA)
    if (tid < 32) {
        int c0 = g_cntp[tid] + g_cntp[tid + 32];
        #pragma unroll
        for (int o = 16; o > 0; o >>= 1) c0 += __shfl_xor_sync(0xffffffffu, c0, o);
        if (tid == 0) is4_sh = (c0 != BB);
    }
    __syncthreads();                   // ONLY block barrier in this kernel
    const bool is4 = is4_sh;

    // stop index for batch b (warp-local scan + max reduce)
    int stop = 0;
    if (is4) {
        const unsigned* m4 = (const unsigned*)mask;
        #pragma unroll
        for (int k = 0; k < TT / 32; k++) {
            int t = l + 32 * k;
            if (m4[t * BB + b]) stop = t;
        }
    } else {
        #pragma unroll
        for (int k = 0; k < TT / 32; k++) {
            int t = l + 32 * k;
            if (mask[t * BB + b]) stop = t;
        }
    }
    #pragma unroll
    for (int o = 16; o > 0; o >>= 1) stop = max(stop, __shfl_xor_sync(0xffffffffu, stop, o));

    // E = exp(trans) in fp16 pairs: e2a[k]=(E[k][l],E[k+32][l]), e2b for l+32
    __half2 e2a[32], e2b[32];
    #pragma unroll
    for (int k = 0; k < 32; k++) {
        e2a[k] = __floats2half2_rn(ex2f_(trans[k*KK + l     ] * LOG2E),
                                   ex2f_(trans[(k+32)*KK + l ] * LOG2E));
        e2b[k] = __floats2half2_rn(ex2f_(trans[k*KK + l + 32 ] * LOG2E),
                                   ex2f_(trans[(k+32)*KK + l+32] * LOG2E));
    }

    const float* ep0 = emits + b * KK + l;
    const float* ep1 = ep0 + 32;
    float R0 = ex2f_((alpha0[l]      + ep0[0]) * LOG2E);
    float R1 = ex2f_((alpha0[l + 32] + ep1[0]) * LOG2E);
    int C2i = 0;

    // normalize initial alpha by CURRENT warp max exponent (exact scale)
    float P0, P1;
    {
        int e = (int)(__float_as_uint(fmaxf(R0, R1)) >> 23);
        int m = __reduce_max_sync(0xffffffffu, e);
        C2i += m;
        const float sc = __int_as_float((254 - m) << 23);    // 2^(127-m)
        P0 = R0 * sc; P1 = R1 * sc;
        p_s[w][0][l] = __floats2half2_rn(P0, P1);
    }

    // emit pipeline depth 4, two streams (cols l and l+32)
    float em0 = ex2f_(ep0[min(1, stop) * STRD] * LOG2E);
    float em1 = ex2f_(ep1[min(1, stop) * STRD] * LOG2E);
    float rA0 = ep0[min(2, stop) * STRD], rA1 = ep1[min(2, stop) * STRD];
    float rB0 = ep0[min(3, stop) * STRD], rB1 = ep1[min(3, stop) * STRD];
    float rC0 = ep0[min(4, stop) * STRD], rC1 = ep1[min(4, stop) * STRD];

    __syncwarp();

#define H2(u) (*reinterpret_cast<const __half2*>(&(u)))

    // One step: read p_s[w][RB] (8 LDS.128 = 32 half2), write p_s[w][WB].
#define CRF_STEP(RB, WB, TCUR, EM0, EM1, RN0, RN1, LD0, LD1, NE0, NE1)         \
    {                                                                          \
        const float LD0 = ep0[(long)min((TCUR) + 4, stop) * STRD];             \
        const float LD1 = ep1[(long)min((TCUR) + 4, stop) * STRD];             \
        const uint4* p4 = (const uint4*)p_s[w][RB];                            \
        __half2 z = __float2half2_rn(0.f);                                     \
        __half2 aA0=z,aA1=z,aA2=z,aA3=z, aB0=z,aB1=z,aB2=z,aB3=z;              \
        _Pragma("unroll")                                                      \
        for (int i = 0; i < 8; i++) {                                          \
            uint4 q = p4[i];                                                   \
            aA0 = __hfma2(H2(q.x), e2a[4*i+0], aA0);                           \
            aB0 = __hfma2(H2(q.x), e2b[4*i+0], aB0);                           \
            aA1 = __hfma2(H2(q.y), e2a[4*i+1], aA1);                           \
            aB1 = __hfma2(H2(q.y), e2b[4*i+1], aB1);                           \
            aA2 = __hfma2(H2(q.z), e2a[4*i+2], aA2);                           \
            aB2 = __hfma2(H2(q.z), e2b[4*i+2], aB2);                           \
            aA3 = __hfma2(H2(q.w), e2a[4*i+3], aA3);                           \
            aB3 = __hfma2(H2(q.w), e2b[4*i+3], aB3);                           \
        }                                                                      \
        __half2 hA = __hadd2(__hadd2(aA0, aA1), __hadd2(aA2, aA3));            \
        __half2 hB = __hadd2(__hadd2(aB0, aB1), __hadd2(aB2, aB3));            \
        float2 fa = __half22float2(hA);                                        \
        float2 fb = __half22float2(hB);                                        \
        const float Rn0 = (fa.x + fa.y) * (EM0);                               \
        const float Rn1 = (fb.x + fb.y) * (EM1);                               \
        int e_ = (int)(__float_as_uint(fmaxf(Rn0, Rn1)) >> 23);                \
        int m_ = __reduce_max_sync(0xffffffffu, e_);   /* single REDUX */      \
        C2i += m_;                                                             \
        const float sc_ = __int_as_float((254 - m_) << 23);  /* exact 2^.. */  \
        P0 = Rn0 * sc_; P1 = Rn1 * sc_;                                        \
        p_s[w][WB][l] = __floats2half2_rn(P0, P1);                             \
        __syncwarp();                                                          \
        const float NE0 = ex2f_((RN0) * LOG2E);      /* post-sync, private */  \
        const float NE1 = ex2f_((RN1) * LOG2E);                                \
        (void)NE0; (void)NE1;

#define CRF_END }

    int t = 1;
    for (; t + 1 <= stop; t += 2) {
        CRF_STEP(0, 1, t,     em0, em1, rA0, rA1, ld0, ld1, ne0, ne1)
        CRF_STEP(1, 0, t + 1, ne0, ne1, rB0, rB1, ld2, ld3, ne2, ne3)
        em0 = ne2; em1 = ne3;
        rA0 = rC0; rA1 = rC1;
        rB0 = ld0; rB1 = ld1;
        rC0 = ld2; rC1 = ld3;
        CRF_END CRF_END
    }
    if (t <= stop) {
        CRF_STEP(0, 1, t, em0, em1, rA0, rA1, lde0, lde1, nee0, nee1)
        CRF_END
    }
#undef CRF_STEP
#undef CRF_END
#undef H2

    // per-b logZ (warp-local, fp32 finals)
    float v = P0 + P1;
    #pragma unroll
    for (int o = 16; o > 0; o >>= 1) v += __shfl_xor_sync(0xffffffffu, v, o);
    int last = 0;
    if (l == 0) {
        const float C2 = (float)(C2i - 127 * (stop + 1));
        g_partial[b] = LN2 * (C2 + lg2f_(v));
        __threadfence();
        last = (atomicAdd(&g_done, 1) == BB - 1);
    }
    last = __shfl_sync(0xffffffffu, last, 0);

    if (last) {                        // deterministic 512->1 sum, one warp
        __threadfence();
        float s = 0.f;
        #pragma unroll
        for (int k = 0; k < BB / 32; k++) s += g_partial[l + 32 * k];
        #pragma unroll
        for (int o = 16; o > 0; o >>= 1) s += __shfl_xor_sync(0xffffffffu, s, o);
        if (l == 0) out[0] = s;
    }
}

extern "C" void kernel_launch(void* const* d_in, const int* in_sizes, int n_in,
                              void* d_out, int out_size)
{
    // Identify inputs by element count (robust to metadata ordering):
    // emits 16777216, mask 262144, trans 4096, alpha0 64.
    const float*         emits  = 0;
    const unsigned char* mask   = 0;
    const float*         trans  = 0;
    const float*         alpha0 = 0;
    for (int i = 0; i < n_in; i++) {
        switch (in_sizes[i]) {
            case 16777216: emits  = (const float*)d_in[i];         break;
            case   262144: mask   = (const unsigned char*)d_in[i]; break;
            case     4096: trans  = (const float*)d_in[i];         break;
            case       64: alpha0 = (const float*)d_in[i];         break;
        }
    }
    detect_kernel<<<64, 256>>>(mask);
    crf_forward_kernel<<<BB / 4, 128>>>(emits, mask, trans, alpha0, (float*)d_out);
}

// round 17
// speedup vs baseline: 1.4888x; 1.1232x over previous
#include <cuda_runtime.h>
#include <cuda_fp16.h>

#define TT 512
#define BB 512
#define KK 64
#define STRD (BB*KK)
#define LOG2E 1.4426950408889634f
#define LN2   0.6931471805599453f

typedef unsigned long long ull;

// scratch (device globals — no allocation)
__device__ float g_partial[BB];
__device__ int   g_cntp[64];   // detect partials, plain-stored each replay
__device__ int   g_done;       // reset by detect block 0 each replay

__device__ __forceinline__ float ex2f_(float x){float y;asm("ex2.approx.f32 %0,%1;":"=f"(y):"f"(x));return y;}
__device__ __forceinline__ float lg2f_(float x){float y;asm("lg2.approx.f32 %0,%1;":"=f"(y):"f"(x));return y;}

#define CNTB(u) ((((u)&0xFFu)!=0)+(((u)&0xFF00u)!=0)+(((u)&0xFF0000u)!=0)+(((u)&0xFF000000u)!=0))

// ---------------------------------------------------------------------------
// Detect: 64 blocks x 256 threads, one uint4 per thread over the first TT*BB
// bytes of the mask (safe under bool/int32/f32 serializations). A 1-byte
// one-hot mask has exactly BB nonzero bytes total. Plain stores: idempotent
// across graph replays. Block 0 also resets the forward completion counter.
// ---------------------------------------------------------------------------
__global__ __launch_bounds__(256) void detect_kernel(const unsigned char* __restrict__ m)
{
    __shared__ int w_s[8];
    const int tid = threadIdx.x;
    if (blockIdx.x == 0 && tid == 0) g_done = 0;
    uint4 v = ((const uint4*)m)[blockIdx.x * 256 + tid];
    int local = CNTB(v.x) + CNTB(v.y) + CNTB(v.z) + CNTB(v.w);
    #pragma unroll
    for (int o = 16; o > 0; o >>= 1) local += __shfl_xor_sync(0xffffffffu, local, o);
    if ((tid & 31) == 0) w_s[tid >> 5] = local;
    __syncthreads();
    if (tid == 0) {
        int s = 0;
        #pragma unroll
        for (int k = 0; k < 8; k++) s += w_s[k];
        g_cntp[blockIdx.x] = s;
    }
}

// ---------------------------------------------------------------------------
// Forward: 128 CTAs x 128 threads; warp w INDEPENDENTLY runs batch 4*cta+w
// (only __syncwarp in the loop; one warp per SMSP chip-wide).
// FP16 matvec (HFMA2 rt2 = 2 MACs/slot, 2x fp32 MAC rate):
//   Q stored as 32 x half2, slot k = (Q_k, Q_{k+32}), CURRENT-MAX normalized
//   (Qmax in [1,2)) -> fp16 sum <= 2*90*64 ~ 11.5k << 65504: no overflow.
//   E prepacked half2 e2a/e2b[k] = (E[k][j], E[k+32][j]).
// Per step: S (fp16) -> R = S*em (fp32) -> m = REDUX.MAX of exponent(R)
//   -> Q = R*2^(127-m) exact; C2i += m (exact int).
// Invariant: log2 alpha_j = lg2(Q_j) + (C2i - 127*(t+1)).
// Final per-b: LN2*((C2i-127*(stop+1)) + lg2(sum_j Q_j)). Last warp: 512->1.
// t-loop unrolled x4 with explicit emit-register rotation (3 movs / 4 steps);
// both emit streams share ONE clamped offset (same-base + imm-32 addressing).
// ---------------------------------------------------------------------------
__global__ __launch_bounds__(128, 1)
void crf_forward_kernel(const float* __restrict__ emits,
                        const unsigned char* __restrict__ mask,
                        const float* __restrict__ trans,
                        const float* __restrict__ alpha0,
                        float* __restrict__ out)
{
    __shared__ __align__(16) __half2 p_s[4][2][32];   // [warp][buf][pair-slot]
    __shared__ int is4_sh;

    const int tid  = threadIdx.x;
    const int w    = tid >> 5;
    const int l    = tid & 31;
    const int b    = 4 * blockIdx.x + w;

    // mask dtype: warp 0 sums the 64 detect partials (once per CTA)
    if (tid < 32) {
        int c0 = g_cntp[tid] + g_cntp[tid + 32];
        #pragma unroll
        for (int o = 16; o > 0; o >>= 1) c0 += __shfl_xor_sync(0xffffffffu, c0, o);
        if (tid == 0) is4_sh = (c0 != BB);
    }
    __syncthreads();                   // ONLY block barrier in this kernel
    const bool is4 = is4_sh;

    // stop index for batch b (warp-local scan + max reduce)
    int stop = 0;
    if (is4) {
        const unsigned* m4 = (const unsigned*)mask;
        #pragma unroll
        for (int k = 0; k < TT / 32; k++) {
            int t = l + 32 * k;
            if (m4[t * BB + b]) stop = t;
        }
    } else {
        #pragma unroll
        for (int k = 0; k < TT / 32; k++) {
            int t = l + 32 * k;
            if (mask[t * BB + b]) stop = t;
        }
    }
    stop = __reduce_max_sync(0xffffffffu, stop);

    // E = exp(trans) in fp16 pairs: e2a[k]=(E[k][l],E[k+32][l]), e2b for l+32
    __half2 e2a[32], e2b[32];
    #pragma unroll
    for (int k = 0; k < 32; k++) {
        e2a[k] = __floats2half2_rn(ex2f_(trans[k*KK + l     ] * LOG2E),
                                   ex2f_(trans[(k+32)*KK + l ] * LOG2E));
        e2b[k] = __floats2half2_rn(ex2f_(trans[k*KK + l + 32 ] * LOG2E),
                                   ex2f_(trans[(k+32)*KK + l+32] * LOG2E));
    }

    const float* ep0 = emits + b * KK + l;   // stream 1; stream 2 = ep0 + 32
    float R0 = ex2f_((alpha0[l]      + ep0[0])  * LOG2E);
    float R1 = ex2f_((alpha0[l + 32] + ep0[32]) * LOG2E);
    int C2i = 0;

    // normalize initial alpha by CURRENT warp max exponent (exact scale)
    float P0, P1;
    {
        int e = (int)(__float_as_uint(fmaxf(R0, R1)) >> 23);
        int m = __reduce_max_sync(0xffffffffu, e);
        C2i += m;
        const float sc = __int_as_float((254 - m) << 23);    // 2^(127-m)
        P0 = R0 * sc; P1 = R1 * sc;
        p_s[w][0][l] = __floats2half2_rn(P0, P1);
    }

    // emit pipeline depth 4, two streams sharing one clamped offset
    float em0, em1;
    { int o1 = min(1, stop) * STRD; em0 = ex2f_(ep0[o1] * LOG2E); em1 = ex2f_(ep0[o1 + 32] * LOG2E); }
    float rA0, rA1, rB0, rB1, rC0, rC1;
    { int o2 = min(2, stop) * STRD; rA0 = ep0[o2]; rA1 = ep0[o2 + 32]; }
    { int o3 = min(3, stop) * STRD; rB0 = ep0[o3]; rB1 = ep0[o3 + 32]; }
    { int o4 = min(4, stop) * STRD; rC0 = ep0[o4]; rC1 = ep0[o4 + 32]; }

    __syncwarp();

#define H2(u) (*reinterpret_cast<const __half2*>(&(u)))

    // One step: read p_s[w][RB] (8 LDS.128 = 32 half2), write p_s[w][WB].
#define CRF_STEP(RB, WB, TCUR, EM0, EM1, RN0, RN1, LD0, LD1, NE0, NE1)         \
    {                                                                          \
        const int off_ = min((TCUR) + 4, stop) * STRD;   /* shared clamp */    \
        const float LD0 = ep0[off_];                                           \
        const float LD1 = ep0[off_ + 32];                                      \
        const uint4* p4 = (const uint4*)p_s[w][RB];                            \
        __half2 z = __float2half2_rn(0.f);                                     \
        __half2 aA0=z,aA1=z,aA2=z,aA3=z, aB0=z,aB1=z,aB2=z,aB3=z;              \
        _Pragma("unroll")                                                      \
        for (int i = 0; i < 8; i++) {                                          \
            uint4 q = p4[i];                                                   \
            aA0 = __hfma2(H2(q.x), e2a[4*i+0], aA0);                           \
            aB0 = __hfma2(H2(q.x), e2b[4*i+0], aB0);                           \
            aA1 = __hfma2(H2(q.y), e2a[4*i+1], aA1);                           \
            aB1 = __hfma2(H2(q.y), e2b[4*i+1], aB1);                           \
            aA2 = __hfma2(H2(q.z), e2a[4*i+2], aA2);                           \
            aB2 = __hfma2(H2(q.z), e2b[4*i+2], aB2);                           \
            aA3 = __hfma2(H2(q.w), e2a[4*i+3], aA3);                           \
            aB3 = __hfma2(H2(q.w), e2b[4*i+3], aB3);                           \
        }                                                                      \
        __half2 hA = __hadd2(__hadd2(aA0, aA1), __hadd2(aA2, aA3));            \
        __half2 hB = __hadd2(__hadd2(aB0, aB1), __hadd2(aB2, aB3));            \
        float2 fa = __half22float2(hA);                                        \
        float2 fb = __half22float2(hB);                                        \
        const float Rn0 = (fa.x + fa.y) * (EM0);                               \
        const float Rn1 = (fb.x + fb.y) * (EM1);                               \
        int e_ = (int)(__float_as_uint(fmaxf(Rn0, Rn1)) >> 23);                \
        int m_ = __reduce_max_sync(0xffffffffu, e_);   /* single REDUX */      \
        C2i += m_;                                                             \
        const float sc_ = __int_as_float((254 - m_) << 23);  /* exact 2^.. */  \
        P0 = Rn0 * sc_; P1 = Rn1 * sc_;                                        \
        p_s[w][WB][l] = __floats2half2_rn(P0, P1);                             \
        __syncwarp();                                                          \
        const float NE0 = ex2f_((RN0) * LOG2E);      /* post-sync, private */  \
        const float NE1 = ex2f_((RN1) * LOG2E);                                \
        (void)NE0; (void)NE1;

#define CRF_END }

    int t = 1;
    for (; t + 3 <= stop; t += 4) {
        CRF_STEP(0, 1, t,     em0, em1, rA0, rA1, ld0, ld1, ne0, ne1)   // stages em(t+1)
        CRF_STEP(1, 0, t + 1, ne0, ne1, rB0, rB1, ld2, ld3, ne2, ne3)
        CRF_STEP(0, 1, t + 2, ne2, ne3, rC0, rC1, ld4, ld5, ne4, ne5)
        CRF_STEP(1, 0, t + 3, ne4, ne5, ld0, ld1, ld6, ld7, ne6, ne7)
        em0 = ne6; em1 = ne7;                       // rotate (3 mov-pairs / 4 steps)
        rA0 = ld2; rA1 = ld3;
        rB0 = ld4; rB1 = ld5;
        rC0 = ld6; rC1 = ld7;
        CRF_END CRF_END CRF_END CRF_END
    }
    for (; t <= stop; t++) {
        if ((t & 1) == 1) {
            CRF_STEP(0, 1, t, em0, em1, rA0, rA1, lde0, lde1, nee0, nee1)
            em0 = nee0; em1 = nee1;
            rA0 = rB0; rA1 = rB1; rB0 = rC0; rB1 = rC1; rC0 = lde0; rC1 = lde1;
            CRF_END
        } else {
            CRF_STEP(1, 0, t, em0, em1, rA0, rA1, lde0, lde1, nee0, nee1)
            em0 = nee0; em1 = nee1;
            rA0 = rB0; rA1 = rB1; rB0 = rC0; rB1 = rC1; rC0 = lde0; rC1 = lde1;
            CRF_END
        }
    }
#undef CRF_STEP
#undef CRF_END
#undef H2

    // per-b logZ (warp-local, fp32 finals)
    float v = P0 + P1;
    #pragma unroll
    for (int o = 16; o > 0; o >>= 1) v += __shfl_xor_sync(0xffffffffu, v, o);
    int last = 0;
    if (l == 0) {
        const float C2 = (float)(C2i - 127 * (stop + 1));
        g_partial[b] = LN2 * (C2 + lg2f_(v));
        __threadfence();
        last = (atomicAdd(&g_done, 1) == BB - 1);
    }
    last = __shfl_sync(0xffffffffu, last, 0);

    if (last) {                        // deterministic 512->1 sum, one warp
        __threadfence();
        float s = 0.f;
        #pragma unroll
        for (int k = 0; k < BB / 32; k++) s += g_partial[l + 32 * k];
        #pragma unroll
        for (int o = 16; o > 0; o >>= 1) s += __shfl_xor_sync(0xffffffffu, s, o);
        if (l == 0) out[0] = s;
    }
}

extern "C" void kernel_launch(void* const* d_in, const int* in_sizes, int n_in,
                              void* d_out, int out_size)
{
    // Identify inputs by element count (robust to metadata ordering):
    // emits 16777216, mask 262144, trans 4096, alpha0 64.
    const float*         emits  = 0;
    const unsigned char* mask   = 0;
    const float*         trans  = 0;
    const float*         alpha0 = 0;
    for (int i = 0; i < n_in; i++) {
        switch (in_sizes[i]) {
            case 16777216: emits  = (const float*)d_in[i];         break;
            case   262144: mask   = (const unsigned char*)d_in[i]; break;
            case     4096: trans  = (const float*)d_in[i];         break;
            case       64: alpha0 = (const float*)d_in[i];         break;
        }
    }
    detect_kernel<<<64, 256>>>(mask);
    crf_forward_kernel<<<BB / 4, 128>>>(emits, mask, trans, alpha0, (float*)d_out);
}